// round 2
// baseline (speedup 1.0000x reference)
#include <cuda_runtime.h>
#include <cstdint>

// ---------------------------------------------------------------------------
// Decoder: out[b,i,a] = sum_{l<=i} sum_f x[b,l,f] * W_i[l,f,a]
//   x: [128, 12, 4096] f32, W_i: [(i+1), 4096, 768] f32, out: [128, 12, 768] f32
//
// Strategy: 468 partial GEMMs (78 (i,l) pairs x 6 N-tiles of 128), each
// [128 x 4096] @ [4096 x 128] via tf32 mma.sync with fp32 accumulation,
// written to a __device__ scratch; then a deterministic reduction kernel.
// ---------------------------------------------------------------------------

namespace {
constexpr int BATCH  = 128;
constexpr int NL     = 12;
constexpr int DF     = 4096;
constexpr int DA     = 768;
constexpr int NPAIR  = 78;          // sum_{i=0..11} (i+1)
constexpr int NTILES = 6;           // 768 / 128
constexpr int BN     = 128;
constexpr int KC     = 32;          // k-chunk per smem stage
constexpr int KT     = DF / KC;     // 128 iterations

constexpr int AS_STRIDE = KC + 4;   // 36 floats  (conflict-free frag loads)
constexpr int BS_STRIDE = BN + 8;   // 136 floats (conflict-free frag loads)
constexpr int AS_ELEMS  = BATCH * AS_STRIDE;  // 4608
constexpr int BS_ELEMS  = KC * BS_STRIDE;     // 4352
constexpr int STAGE     = AS_ELEMS + BS_ELEMS;
constexpr int SMEM_BYTES = 2 * STAGE * (int)sizeof(float);  // 71680
}

// scratch: partial[pair][b][a]  (30.7 MB)
__device__ float g_partial[(size_t)NPAIR * BATCH * DA];

struct WPtrs { const float* w[NL]; };

__device__ __forceinline__ uint32_t f2tf32(float f) {
    uint32_t u;
    asm("cvt.rna.tf32.f32 %0, %1;" : "=r"(u) : "f"(f));
    return u;
}

__device__ __forceinline__ void cp_async16(float* smem_dst, const float* gmem_src) {
    uint32_t s = (uint32_t)__cvta_generic_to_shared(smem_dst);
    asm volatile("cp.async.cg.shared.global [%0], [%1], 16;\n" :: "r"(s), "l"(gmem_src));
}

__device__ __forceinline__ void mma_tf32(float c[4], const uint32_t a[4], const uint32_t b[2]) {
    asm volatile(
        "mma.sync.aligned.m16n8k8.row.col.f32.tf32.tf32.f32 "
        "{%0,%1,%2,%3}, {%4,%5,%6,%7}, {%8,%9}, {%0,%1,%2,%3};"
        : "+f"(c[0]), "+f"(c[1]), "+f"(c[2]), "+f"(c[3])
        : "r"(a[0]), "r"(a[1]), "r"(a[2]), "r"(a[3]),
          "r"(b[0]), "r"(b[1]));
}

__global__ void __launch_bounds__(256, 2)
gemm_partial_kernel(const float* __restrict__ x, WPtrs wp) {
    extern __shared__ float smem[];

    const int bid   = blockIdx.x;
    const int p     = bid / NTILES;      // (i, l) pair index
    const int ntile = bid % NTILES;

    // decode pair p -> (layer i, slab l)
    int i = 0, tri = 0;
    while (tri + i + 1 <= p) { tri += i + 1; ++i; }
    const int l = p - tri;

    const float* xbase = x + (size_t)l * DF;                          // + b*NL*DF per row
    const float* wbase = wp.w[i] + (size_t)l * DF * DA + ntile * BN;  // [k][n-slice]

    const int t    = threadIdx.x;
    const int lane = t & 31;
    const int warp = t >> 5;
    const int wm   = (warp & 1) << 6;   // 0 or 64   (M within 128)
    const int wn   = (warp >> 1) << 5;  // 0..96     (N within 128)
    const int gid  = lane >> 2;         // 0..7
    const int tg   = lane & 3;          // 0..3

    float acc[4][4][4];
    #pragma unroll
    for (int a = 0; a < 4; a++)
        #pragma unroll
        for (int b = 0; b < 4; b++)
            #pragma unroll
            for (int c = 0; c < 4; c++) acc[a][b][c] = 0.0f;

    auto load_stage = [&](int st, int k0) {
        float* sA = smem + st * STAGE;
        float* sB = sA + AS_ELEMS;
        // A: 128 rows x 32 floats; each row 128B contiguous, 8 threads/row
        #pragma unroll
        for (int it = 0; it < 4; it++) {
            int row = (t >> 3) + it * 32;
            int q   = (t & 7) << 2;
            cp_async16(sA + row * AS_STRIDE + q,
                       xbase + (size_t)row * (NL * DF) + k0 + q);
        }
        // B: 32 rows x 128 floats; each row 512B contiguous, 32 threads/row
        #pragma unroll
        for (int it = 0; it < 4; it++) {
            int k = (t >> 5) + it * 8;
            int q = (t & 31) << 2;
            cp_async16(sB + k * BS_STRIDE + q,
                       wbase + (size_t)(k0 + k) * DA + q);
        }
    };

    load_stage(0, 0);
    asm volatile("cp.async.commit_group;\n" ::: "memory");

    for (int kt = 0; kt < KT; kt++) {
        if (kt + 1 < KT) {
            load_stage((kt + 1) & 1, (kt + 1) * KC);
            asm volatile("cp.async.commit_group;\n" ::: "memory");
            asm volatile("cp.async.wait_group 1;\n" ::: "memory");
        } else {
            asm volatile("cp.async.wait_group 0;\n" ::: "memory");
        }
        __syncthreads();

        const float* sA = smem + (kt & 1) * STAGE;
        const float* sB = sA + AS_ELEMS;

        #pragma unroll
        for (int k8 = 0; k8 < KC / 8; k8++) {
            const int kb = k8 * 8;
            uint32_t af[4][4];
            #pragma unroll
            for (int mt = 0; mt < 4; mt++) {
                int r = wm + mt * 16 + gid;
                af[mt][0] = f2tf32(sA[(size_t)r * AS_STRIDE + kb + tg]);
                af[mt][1] = f2tf32(sA[(size_t)(r + 8) * AS_STRIDE + kb + tg]);
                af[mt][2] = f2tf32(sA[(size_t)r * AS_STRIDE + kb + tg + 4]);
                af[mt][3] = f2tf32(sA[(size_t)(r + 8) * AS_STRIDE + kb + tg + 4]);
            }
            uint32_t bf[4][2];
            #pragma unroll
            for (int nt = 0; nt < 4; nt++) {
                int c = wn + nt * 8 + gid;
                bf[nt][0] = f2tf32(sB[(size_t)(kb + tg) * BS_STRIDE + c]);
                bf[nt][1] = f2tf32(sB[(size_t)(kb + tg + 4) * BS_STRIDE + c]);
            }
            #pragma unroll
            for (int mt = 0; mt < 4; mt++)
                #pragma unroll
                for (int nt = 0; nt < 4; nt++)
                    mma_tf32(acc[mt][nt], af[mt], bf[nt]);
        }
        __syncthreads();
    }

    // epilogue: write [128 x 128] partial tile
    float* pbase = g_partial + (size_t)p * (BATCH * DA) + ntile * BN;
    #pragma unroll
    for (int mt = 0; mt < 4; mt++) {
        int r = wm + mt * 16 + gid;
        #pragma unroll
        for (int nt = 0; nt < 4; nt++) {
            int c = wn + nt * 8 + (tg << 1);
            *reinterpret_cast<float2*>(pbase + (size_t)r * DA + c) =
                make_float2(acc[mt][nt][0], acc[mt][nt][1]);
            *reinterpret_cast<float2*>(pbase + (size_t)(r + 8) * DA + c) =
                make_float2(acc[mt][nt][2], acc[mt][nt][3]);
        }
    }
}

__global__ void reduce_kernel(float* __restrict__ out) {
    int idx = blockIdx.x * blockDim.x + threadIdx.x;
    const int total = BATCH * NL * DA;
    if (idx >= total) return;
    int n = idx % DA;
    int i = (idx / DA) % NL;
    int b = idx / (DA * NL);
    int tri = i * (i + 1) / 2;
    const float* base = g_partial + (size_t)tri * (BATCH * DA) + (size_t)b * DA + n;
    float s = 0.0f;
    #pragma unroll 1
    for (int l = 0; l <= i; l++) s += base[(size_t)l * (BATCH * DA)];
    out[idx] = s;
}

extern "C" void kernel_launch(void* const* d_in, const int* in_sizes, int n_in,
                              void* d_out, int out_size) {
    const float* x = (const float*)d_in[0];
    WPtrs wp;
    for (int i = 0; i < NL; i++) wp.w[i] = (const float*)d_in[1 + i];

    cudaFuncSetAttribute(gemm_partial_kernel,
                         cudaFuncAttributeMaxDynamicSharedMemorySize, SMEM_BYTES);

    gemm_partial_kernel<<<NPAIR * NTILES, 256, SMEM_BYTES>>>(x, wp);

    const int total = BATCH * NL * DA;
    reduce_kernel<<<(total + 255) / 256, 256>>>((float*)d_out);
}

// round 3
// speedup vs baseline: 1.0030x; 1.0030x over previous
#include <cuda_runtime.h>
#include <cstdint>

// ---------------------------------------------------------------------------
// Decoder: out[b,i,a] = sum_{l<=i} sum_f x[b,l,f] * W_i[l,f,a]
//   x: [128, 12, 4096] f32, W_i: [(i+1), 4096, 768] f32, out: [128, 12, 768] f32
//
// Strategy: 468 partial GEMMs (78 (i,l) pairs x 6 N-tiles of 128), each
// [128 x 4096] @ [4096 x 128] via tf32 mma.sync with fp32 accumulation,
// written to a __device__ scratch; then a deterministic reduction kernel.
// ---------------------------------------------------------------------------

namespace {
constexpr int BATCH  = 128;
constexpr int NL     = 12;
constexpr int DF     = 4096;
constexpr int DA     = 768;
constexpr int NPAIR  = 78;          // sum_{i=0..11} (i+1)
constexpr int NTILES = 6;           // 768 / 128
constexpr int BN     = 128;
constexpr int KC     = 32;          // k-chunk per smem stage
constexpr int KT     = DF / KC;     // 128 iterations

constexpr int AS_STRIDE = KC + 4;   // 36 floats  (conflict-free frag loads)
constexpr int BS_STRIDE = BN + 8;   // 136 floats (conflict-free frag loads)
constexpr int AS_ELEMS  = BATCH * AS_STRIDE;  // 4608
constexpr int BS_ELEMS  = KC * BS_STRIDE;     // 4352
constexpr int STAGE     = AS_ELEMS + BS_ELEMS;
constexpr int SMEM_BYTES = 2 * STAGE * (int)sizeof(float);  // 71680
}

// scratch: partial[pair][b][a]  (30.7 MB)
__device__ float g_partial[(size_t)NPAIR * BATCH * DA];

struct WPtrs { const float* w[NL]; };

__device__ __forceinline__ uint32_t f2tf32(float f) {
    uint32_t u;
    asm("cvt.rna.tf32.f32 %0, %1;" : "=r"(u) : "f"(f));
    return u;
}

__device__ __forceinline__ void cp_async16(float* smem_dst, const float* gmem_src) {
    uint32_t s = (uint32_t)__cvta_generic_to_shared(smem_dst);
    asm volatile("cp.async.cg.shared.global [%0], [%1], 16;\n" :: "r"(s), "l"(gmem_src));
}

__device__ __forceinline__ void mma_tf32(float c[4], const uint32_t a[4], const uint32_t b[2]) {
    asm volatile(
        "mma.sync.aligned.m16n8k8.row.col.f32.tf32.tf32.f32 "
        "{%0,%1,%2,%3}, {%4,%5,%6,%7}, {%8,%9}, {%0,%1,%2,%3};"
        : "+f"(c[0]), "+f"(c[1]), "+f"(c[2]), "+f"(c[3])
        : "r"(a[0]), "r"(a[1]), "r"(a[2]), "r"(a[3]),
          "r"(b[0]), "r"(b[1]));
}

__global__ void __launch_bounds__(256, 2)
gemm_partial_kernel(const float* __restrict__ x, WPtrs wp) {
    extern __shared__ float smem[];

    const int bid   = blockIdx.x;
    const int p     = bid / NTILES;      // (i, l) pair index
    const int ntile = bid % NTILES;

    // decode pair p -> (layer i, slab l)
    int i = 0, tri = 0;
    while (tri + i + 1 <= p) { tri += i + 1; ++i; }
    const int l = p - tri;

    const float* xbase = x + (size_t)l * DF;                          // + b*NL*DF per row
    const float* wbase = wp.w[i] + (size_t)l * DF * DA + ntile * BN;  // [k][n-slice]

    const int t    = threadIdx.x;
    const int lane = t & 31;
    const int warp = t >> 5;
    const int wm   = (warp & 1) << 6;   // 0 or 64   (M within 128)
    const int wn   = (warp >> 1) << 5;  // 0..96     (N within 128)
    const int gid  = lane >> 2;         // 0..7
    const int tg   = lane & 3;          // 0..3

    float acc[4][4][4];
    #pragma unroll
    for (int a = 0; a < 4; a++)
        #pragma unroll
        for (int b = 0; b < 4; b++)
            #pragma unroll
            for (int c = 0; c < 4; c++) acc[a][b][c] = 0.0f;

    auto load_stage = [&](int st, int k0) {
        float* sA = smem + st * STAGE;
        float* sB = sA + AS_ELEMS;
        // A: 128 rows x 32 floats; each row 128B contiguous, 8 threads/row
        #pragma unroll
        for (int it = 0; it < 4; it++) {
            int row = (t >> 3) + it * 32;
            int q   = (t & 7) << 2;
            cp_async16(sA + row * AS_STRIDE + q,
                       xbase + (size_t)row * (NL * DF) + k0 + q);
        }
        // B: 32 rows x 128 floats; each row 512B contiguous, 32 threads/row
        #pragma unroll
        for (int it = 0; it < 4; it++) {
            int k = (t >> 5) + it * 8;
            int q = (t & 31) << 2;
            cp_async16(sB + k * BS_STRIDE + q,
                       wbase + (size_t)(k0 + k) * DA + q);
        }
    };

    load_stage(0, 0);
    asm volatile("cp.async.commit_group;\n" ::: "memory");

    for (int kt = 0; kt < KT; kt++) {
        if (kt + 1 < KT) {
            load_stage((kt + 1) & 1, (kt + 1) * KC);
            asm volatile("cp.async.commit_group;\n" ::: "memory");
            asm volatile("cp.async.wait_group 1;\n" ::: "memory");
        } else {
            asm volatile("cp.async.wait_group 0;\n" ::: "memory");
        }
        __syncthreads();

        const float* sA = smem + (kt & 1) * STAGE;
        const float* sB = sA + AS_ELEMS;

        #pragma unroll
        for (int k8 = 0; k8 < KC / 8; k8++) {
            const int kb = k8 * 8;
            uint32_t af[4][4];
            #pragma unroll
            for (int mt = 0; mt < 4; mt++) {
                int r = wm + mt * 16 + gid;
                af[mt][0] = f2tf32(sA[(size_t)r * AS_STRIDE + kb + tg]);
                af[mt][1] = f2tf32(sA[(size_t)(r + 8) * AS_STRIDE + kb + tg]);
                af[mt][2] = f2tf32(sA[(size_t)r * AS_STRIDE + kb + tg + 4]);
                af[mt][3] = f2tf32(sA[(size_t)(r + 8) * AS_STRIDE + kb + tg + 4]);
            }
            uint32_t bf[4][2];
            #pragma unroll
            for (int nt = 0; nt < 4; nt++) {
                int c = wn + nt * 8 + gid;
                bf[nt][0] = f2tf32(sB[(size_t)(kb + tg) * BS_STRIDE + c]);
                bf[nt][1] = f2tf32(sB[(size_t)(kb + tg + 4) * BS_STRIDE + c]);
            }
            #pragma unroll
            for (int mt = 0; mt < 4; mt++)
                #pragma unroll
                for (int nt = 0; nt < 4; nt++)
                    mma_tf32(acc[mt][nt], af[mt], bf[nt]);
        }
        __syncthreads();
    }

    // epilogue: write [128 x 128] partial tile
    float* pbase = g_partial + (size_t)p * (BATCH * DA) + ntile * BN;
    #pragma unroll
    for (int mt = 0; mt < 4; mt++) {
        int r = wm + mt * 16 + gid;
        #pragma unroll
        for (int nt = 0; nt < 4; nt++) {
            int c = wn + nt * 8 + (tg << 1);
            *reinterpret_cast<float2*>(pbase + (size_t)r * DA + c) =
                make_float2(acc[mt][nt][0], acc[mt][nt][1]);
            *reinterpret_cast<float2*>(pbase + (size_t)(r + 8) * DA + c) =
                make_float2(acc[mt][nt][2], acc[mt][nt][3]);
        }
    }
}

__global__ void reduce_kernel(float* __restrict__ out) {
    int idx = blockIdx.x * blockDim.x + threadIdx.x;
    const int total = BATCH * NL * DA;
    if (idx >= total) return;
    int n = idx % DA;
    int i = (idx / DA) % NL;
    int b = idx / (DA * NL);
    int tri = i * (i + 1) / 2;
    const float* base = g_partial + (size_t)tri * (BATCH * DA) + (size_t)b * DA + n;
    float s = 0.0f;
    #pragma unroll 1
    for (int l = 0; l <= i; l++) s += base[(size_t)l * (BATCH * DA)];
    out[idx] = s;
}

extern "C" void kernel_launch(void* const* d_in, const int* in_sizes, int n_in,
                              void* d_out, int out_size) {
    const float* x = (const float*)d_in[0];
    WPtrs wp;
    for (int i = 0; i < NL; i++) wp.w[i] = (const float*)d_in[1 + i];

    cudaFuncSetAttribute(gemm_partial_kernel,
                         cudaFuncAttributeMaxDynamicSharedMemorySize, SMEM_BYTES);

    gemm_partial_kernel<<<NPAIR * NTILES, 256, SMEM_BYTES>>>(x, wp);

    const int total = BATCH * NL * DA;
    reduce_kernel<<<(total + 255) / 256, 256>>>((float*)d_out);
}